// round 3
// baseline (speedup 1.0000x reference)
#include <cuda_runtime.h>

#define N_POINTS    32768
#define EMB         64
#define NUM_CLASSES 50
#define NUM_HOUSES  5
#define NUM_WIN     6            // NUM_WINDOWS + 1 (last = frame)
#define BOXES       (NUM_HOUSES * NUM_WIN)   // 30

// Output: data (N*64) | contains (50*N) | dists (50*30*N)
#define OUT_CONTAINS ((size_t)N_POINTS * EMB)
#define OUT_DISTS    (OUT_CONTAINS + (size_t)NUM_CLASSES * N_POINTS)

typedef unsigned long long u64;

__device__ __forceinline__ u64 f32x2_sub(u64 a, u64 b) {
    u64 r; asm("sub.rn.f32x2 %0, %1, %2;" : "=l"(r) : "l"(a), "l"(b)); return r;
}
__device__ __forceinline__ u64 f32x2_add(u64 a, u64 b) {
    u64 r; asm("add.rn.f32x2 %0, %1, %2;" : "=l"(r) : "l"(a), "l"(b)); return r;
}
__device__ __forceinline__ u64 f32x2_mul(u64 a, u64 b) {
    u64 r; asm("mul.rn.f32x2 %0, %1, %2;" : "=l"(r) : "l"(a), "l"(b)); return r;
}
__device__ __forceinline__ u64 f32x2_fma(u64 a, u64 b, u64 c) {
    u64 r; asm("fma.rn.f32x2 %0, %1, %2, %3;" : "=l"(r) : "l"(a), "l"(b), "l"(c)); return r;
}
__device__ __forceinline__ u64 pack2(float x, float y) {
    u64 r; asm("mov.b64 %0, {%1, %2};" : "=l"(r) : "f"(x), "f"(y)); return r;
}
__device__ __forceinline__ void unpack2(u64 v, float& x, float& y) {
    asm("mov.b64 {%0, %1}, %2;" : "=f"(x), "=f"(y) : "l"(v));
}

// One 2-dim step: scalar clamp (FMNMX x4), packed (p-c)^2 accumulate.
#define PAIR_FMA(J, ACC) {                                        \
    const float4 bb = bx[(J)];                                    \
    float px, py; unpack2(p[(J)], px, py);                        \
    const float c0 = fminf(fmaxf(px, bb.x), bb.z);                \
    const float c1 = fminf(fmaxf(py, bb.y), bb.w);                \
    const u64 d = f32x2_sub(p[(J)], pack2(c0, c1));               \
    ACC = f32x2_fma(d, d, ACC); }

#define PAIR_MUL(J, ACC) {                                        \
    const float4 bb = bx[(J)];                                    \
    float px, py; unpack2(p[(J)], px, py);                        \
    const float c0 = fminf(fmaxf(px, bb.x), bb.z);                \
    const float c1 = fminf(fmaxf(py, bb.y), bb.w);                \
    const u64 d = f32x2_sub(p[(J)], pack2(c0, c1));               \
    ACC = f32x2_mul(d, d); }

__global__ __launch_bounds__(256, 4)
void geom_kernel(const float* __restrict__ data,
                 const float* __restrict__ shape,   // [50][5][6][2][64]
                 float* __restrict__ out)
{
    // Interleaved: s_box[box][j] = (lo[2j], lo[2j+1], hi[2j], hi[2j+1])
    __shared__ float4 s_box[BOXES][32];

    const int c   = blockIdx.y;
    const int tid = threadIdx.x;

    // ---- stage this class's 30 boxes, min/max-normalized, interleaved ----
    const float2* sb2 = reinterpret_cast<const float2*>(
        shape + (size_t)c * (BOXES * 2 * EMB));
    #pragma unroll
    for (int e = tid; e < BOXES * 32; e += 256) {
        const int box = e >> 5;
        const int j   = e & 31;
        const float2 a = sb2[box * 64 + j];        // corner 0, dims 2j,2j+1
        const float2 b = sb2[box * 64 + 32 + j];   // corner 1
        s_box[box][j] = make_float4(fminf(a.x, b.x), fminf(a.y, b.y),
                                    fmaxf(a.x, b.x), fmaxf(a.y, b.y));
    }

    // ---- data passthrough (only class-slice 0): clean linear block copy ----
    if (blockIdx.y == 0) {
        // this block covers 64 points = 4096 floats = 1024 float4
        const float4* src = reinterpret_cast<const float4*>(
            data + (size_t)blockIdx.x * 64 * EMB);
        float4* dst = reinterpret_cast<float4*>(
            out + (size_t)blockIdx.x * 64 * EMB);
        #pragma unroll
        for (int k = 0; k < 4; k++)
            dst[tid + 256 * k] = src[tid + 256 * k];
    }
    __syncthreads();

    // ---- 4 threads per point: lane = g*8 + i, g = dim-group, i = point ----
    const int lane = tid & 31;
    const int warp = tid >> 5;
    const int g    = lane >> 3;   // dim group 0..3 -> dims [g*16, g*16+16)
    const int i    = lane & 7;    // point within warp's octet
    const int n    = blockIdx.x * 64 + warp * 8 + i;

    // 16 dims = 8 packed f32x2
    u64 p[8];
    const ulonglong2* dp = reinterpret_cast<const ulonglong2*>(
        data + (size_t)n * EMB + g * 16);
    #pragma unroll
    for (int k = 0; k < 4; k++) {
        const ulonglong2 v = dp[k];
        p[2 * k]     = v.x;
        p[2 * k + 1] = v.y;
    }

    float* __restrict__ out_dists = out + OUT_DISTS
                                  + (size_t)c * BOXES * N_POINTS + n;

    bool town = false;
    int box = 0;
    #pragma unroll 1
    for (int h = 0; h < NUM_HOUSES; h++) {
        bool anyw = false, frame = false;
        #pragma unroll 2
        for (int w = 0; w < NUM_WIN; w++, box++) {
            const float4* bx = &s_box[box][g * 8];
            u64 a0, a1;
            PAIR_MUL(0, a0) PAIR_MUL(1, a1)
            #pragma unroll
            for (int j = 2; j < 8; j += 2) {
                PAIR_FMA(j + 0, a0)
                PAIR_FMA(j + 1, a1)
            }
            const u64 s = f32x2_add(a0, a1);
            float sx, sy; unpack2(s, sx, sy);
            float sq = sx + sy;
            // reduce partial sums across the 4 dim-groups (lanes xor 8, 16)
            sq += __shfl_xor_sync(0xffffffffu, sq, 8);
            sq += __shfl_xor_sync(0xffffffffu, sq, 16);

            // inside <=> clamped == p in every dim <=> sq == 0 (exact;
            // partials are >= 0, so total is 0 iff every partial is 0)
            const bool ins = (sq == 0.0f);
            if (w < NUM_WIN - 1) anyw |= ins;
            else                 frame = ins;

            if (g == 0) {
                float dist;
                asm("sqrt.approx.f32 %0, %1;" : "=f"(dist) : "f"(sq));
                out_dists[(size_t)box * N_POINTS] = dist;
            }
        }
        town |= (frame && !anyw);
    }

    if (g == 0)
        out[OUT_CONTAINS + (size_t)c * N_POINTS + n] = town ? 1.0f : 0.0f;
}

extern "C" void kernel_launch(void* const* d_in, const int* in_sizes, int n_in,
                              void* d_out, int out_size) {
    const float* data  = (const float*)d_in[0];
    const float* shape = (const float*)d_in[1];
    float* out = (float*)d_out;

    dim3 grid(N_POINTS / 64, NUM_CLASSES);
    geom_kernel<<<grid, 256>>>(data, shape, out);
}

// round 4
// speedup vs baseline: 1.2658x; 1.2658x over previous
#include <cuda_runtime.h>

#define N_POINTS    32768
#define EMB         64
#define NUM_CLASSES 50
#define NUM_HOUSES  5
#define NUM_WIN     6            // NUM_WINDOWS + 1 (last = frame)
#define BOXES       (NUM_HOUSES * NUM_WIN)   // 30

// Output: data (N*64) | contains (50*N) | dists (50*30*N)
#define OUT_CONTAINS ((size_t)N_POINTS * EMB)
#define OUT_DISTS    (OUT_CONTAINS + (size_t)NUM_CLASSES * N_POINTS)

typedef unsigned long long u64;

__device__ __forceinline__ u64 f32x2_sub(u64 a, u64 b) {
    u64 r; asm("sub.rn.f32x2 %0, %1, %2;" : "=l"(r) : "l"(a), "l"(b)); return r;
}
__device__ __forceinline__ u64 f32x2_add(u64 a, u64 b) {
    u64 r; asm("add.rn.f32x2 %0, %1, %2;" : "=l"(r) : "l"(a), "l"(b)); return r;
}
__device__ __forceinline__ u64 f32x2_mul(u64 a, u64 b) {
    u64 r; asm("mul.rn.f32x2 %0, %1, %2;" : "=l"(r) : "l"(a), "l"(b)); return r;
}
__device__ __forceinline__ u64 f32x2_fma(u64 a, u64 b, u64 c) {
    u64 r; asm("fma.rn.f32x2 %0, %1, %2, %3;" : "=l"(r) : "l"(a), "l"(b), "l"(c)); return r;
}
__device__ __forceinline__ u64 pack2(float x, float y) {
    u64 r; asm("mov.b64 %0, {%1, %2};" : "=l"(r) : "f"(x), "f"(y)); return r;
}
__device__ __forceinline__ void unpack2(u64 v, float& x, float& y) {
    asm("mov.b64 {%0, %1}, %2;" : "=f"(x), "=f"(y) : "l"(v));
}

// One 2-dim step: scalar clamp (FMNMX x4), packed (p-c)^2 accumulate.
#define PAIR_FMA(J, ACC) {                                        \
    const float4 bb = bx[(J)];                                    \
    float px, py; unpack2(p[(J)], px, py);                        \
    const float c0 = fminf(fmaxf(px, bb.x), bb.z);                \
    const float c1 = fminf(fmaxf(py, bb.y), bb.w);                \
    const u64 d = f32x2_sub(p[(J)], pack2(c0, c1));               \
    ACC = f32x2_fma(d, d, ACC); }

#define PAIR_MUL(J, ACC) {                                        \
    const float4 bb = bx[(J)];                                    \
    float px, py; unpack2(p[(J)], px, py);                        \
    const float c0 = fminf(fmaxf(px, bb.x), bb.z);                \
    const float c1 = fminf(fmaxf(py, bb.y), bb.w);                \
    const u64 d = f32x2_sub(p[(J)], pack2(c0, c1));               \
    ACC = f32x2_mul(d, d); }

#define GRP_STRIDE 9   // 8 data float4 + 1 pad -> group stride 144B (4 banks skew)

__global__ __launch_bounds__(256, 4)
void geom_kernel(const float* __restrict__ data,
                 const float* __restrict__ shape,   // [50][5][6][2][64]
                 float* __restrict__ out)
{
    // s_box[box][group][slot] = (lo[2j],lo[2j+1],hi[2j],hi[2j+1]),
    // j = group*8 + slot. Padded: group stride = 9 float4 = 144B, so the
    // 4 lane-octets (one per group) hit disjoint bank quads -> conflict-free.
    __shared__ float4 s_box[BOXES][4 * GRP_STRIDE];

    const int c   = blockIdx.y;
    const int tid = threadIdx.x;

    // ---- stage this class's 30 boxes, min/max-normalized, interleaved ----
    const float2* sb2 = reinterpret_cast<const float2*>(
        shape + (size_t)c * (BOXES * 2 * EMB));
    #pragma unroll
    for (int e = tid; e < BOXES * 32; e += 256) {
        const int box = e >> 5;
        const int j   = e & 31;
        const float2 a = sb2[box * 64 + j];        // corner 0, dims 2j,2j+1
        const float2 b = sb2[box * 64 + 32 + j];   // corner 1
        s_box[box][(j >> 3) * GRP_STRIDE + (j & 7)] =
            make_float4(fminf(a.x, b.x), fminf(a.y, b.y),
                        fmaxf(a.x, b.x), fmaxf(a.y, b.y));
    }

    // ---- data passthrough (only class-slice 0): clean linear block copy ----
    if (blockIdx.y == 0) {
        // this block covers 64 points = 4096 floats = 1024 float4
        const float4* src = reinterpret_cast<const float4*>(
            data + (size_t)blockIdx.x * 64 * EMB);
        float4* dst = reinterpret_cast<float4*>(
            out + (size_t)blockIdx.x * 64 * EMB);
        #pragma unroll
        for (int k = 0; k < 4; k++)
            dst[tid + 256 * k] = src[tid + 256 * k];
    }
    __syncthreads();

    // ---- 4 threads per point: lane = g*8 + i, g = dim-group, i = point ----
    const int lane = tid & 31;
    const int warp = tid >> 5;
    const int g    = lane >> 3;   // dim group 0..3 -> dims [g*16, g*16+16)
    const int i    = lane & 7;    // point within warp's octet
    const int n    = blockIdx.x * 64 + warp * 8 + i;

    // 16 dims = 8 packed f32x2
    u64 p[8];
    const ulonglong2* dp = reinterpret_cast<const ulonglong2*>(
        data + (size_t)n * EMB + g * 16);
    #pragma unroll
    for (int k = 0; k < 4; k++) {
        const ulonglong2 v = dp[k];
        p[2 * k]     = v.x;
        p[2 * k + 1] = v.y;
    }

    float* __restrict__ out_dists = out + OUT_DISTS
                                  + (size_t)c * BOXES * N_POINTS + n;

    bool town = false;
    int box = 0;
    #pragma unroll 1
    for (int h = 0; h < NUM_HOUSES; h++) {
        bool anyw = false, frame = false;
        #pragma unroll 2
        for (int w = 0; w < NUM_WIN; w++, box++) {
            const float4* bx = &s_box[box][g * GRP_STRIDE];
            u64 a0, a1;
            PAIR_MUL(0, a0) PAIR_MUL(1, a1)
            #pragma unroll
            for (int j = 2; j < 8; j += 2) {
                PAIR_FMA(j + 0, a0)
                PAIR_FMA(j + 1, a1)
            }
            const u64 s = f32x2_add(a0, a1);
            float sx, sy; unpack2(s, sx, sy);
            float sq = sx + sy;
            // reduce partial sums across the 4 dim-groups (lanes xor 8, 16)
            sq += __shfl_xor_sync(0xffffffffu, sq, 8);
            sq += __shfl_xor_sync(0xffffffffu, sq, 16);

            // inside <=> clamped == p in every dim <=> sq == 0 (exact;
            // partials are >= 0, so total is 0 iff every partial is 0)
            const bool ins = (sq == 0.0f);
            if (w < NUM_WIN - 1) anyw |= ins;
            else                 frame = ins;

            if (g == 0) {
                float dist;
                asm("sqrt.approx.f32 %0, %1;" : "=f"(dist) : "f"(sq));
                out_dists[(size_t)box * N_POINTS] = dist;
            }
        }
        town |= (frame && !anyw);
    }

    if (g == 0)
        out[OUT_CONTAINS + (size_t)c * N_POINTS + n] = town ? 1.0f : 0.0f;
}

extern "C" void kernel_launch(void* const* d_in, const int* in_sizes, int n_in,
                              void* d_out, int out_size) {
    const float* data  = (const float*)d_in[0];
    const float* shape = (const float*)d_in[1];
    float* out = (float*)d_out;

    dim3 grid(N_POINTS / 64, NUM_CLASSES);
    geom_kernel<<<grid, 256>>>(data, shape, out);
}

// round 5
// speedup vs baseline: 1.4967x; 1.1824x over previous
#include <cuda_runtime.h>

#define N_POINTS    32768
#define EMB         64
#define NUM_CLASSES 50
#define NUM_HOUSES  5
#define NUM_WIN     6            // NUM_WINDOWS + 1 (last = frame)
#define BOXES       (NUM_HOUSES * NUM_WIN)   // 30

// Output: data (N*64) | contains (50*N) | dists (50*30*N)
#define OUT_CONTAINS ((size_t)N_POINTS * EMB)
#define OUT_DISTS    (OUT_CONTAINS + (size_t)NUM_CLASSES * N_POINTS)

typedef unsigned long long u64;

__device__ __forceinline__ u64 f32x2_sub(u64 a, u64 b) {
    u64 r; asm("sub.rn.f32x2 %0, %1, %2;" : "=l"(r) : "l"(a), "l"(b)); return r;
}
__device__ __forceinline__ u64 f32x2_add(u64 a, u64 b) {
    u64 r; asm("add.rn.f32x2 %0, %1, %2;" : "=l"(r) : "l"(a), "l"(b)); return r;
}
__device__ __forceinline__ u64 f32x2_mul(u64 a, u64 b) {
    u64 r; asm("mul.rn.f32x2 %0, %1, %2;" : "=l"(r) : "l"(a), "l"(b)); return r;
}
__device__ __forceinline__ u64 f32x2_fma(u64 a, u64 b, u64 c) {
    u64 r; asm("fma.rn.f32x2 %0, %1, %2, %3;" : "=l"(r) : "l"(a), "l"(b), "l"(c)); return r;
}
__device__ __forceinline__ u64 pack2(float x, float y) {
    u64 r; asm("mov.b64 %0, {%1, %2};" : "=l"(r) : "f"(x), "f"(y)); return r;
}
__device__ __forceinline__ void unpack2(u64 v, float& x, float& y) {
    asm("mov.b64 {%0, %1}, %2;" : "=f"(x), "=f"(y) : "l"(v));
}

// One 2-dim step: scalar clamp (FMNMX x4), packed (p-c)^2 accumulate.
#define PAIR_FMA(J, ACC) {                                        \
    const float4 bb = bx[(J)];                                    \
    float px, py; unpack2(p[(J)], px, py);                        \
    const float c0 = fminf(fmaxf(px, bb.x), bb.z);                \
    const float c1 = fminf(fmaxf(py, bb.y), bb.w);                \
    const u64 d = f32x2_sub(p[(J)], pack2(c0, c1));               \
    ACC = f32x2_fma(d, d, ACC); }

#define PAIR_MUL(J, ACC) {                                        \
    const float4 bb = bx[(J)];                                    \
    float px, py; unpack2(p[(J)], px, py);                        \
    const float c0 = fminf(fmaxf(px, bb.x), bb.z);                \
    const float c1 = fminf(fmaxf(py, bb.y), bb.w);                \
    const u64 d = f32x2_sub(p[(J)], pack2(c0, c1));               \
    ACC = f32x2_mul(d, d); }

#define GRP_STRIDE 17  // 16 data float4 + 1 pad -> 272B group skew (4 banks)

__global__ __launch_bounds__(256, 3)
void geom_kernel(const float* __restrict__ data,
                 const float* __restrict__ shape,   // [50][5][6][2][64]
                 float* __restrict__ out)
{
    // s_box[box][g*17 + slot] = (lo[2j],lo[2j+1],hi[2j],hi[2j+1]),
    // j = g*16 + slot. The two half-warp broadcast addresses differ by
    // 17 float4 = 68 words == 4 banks (mod 32) -> disjoint bank quads.
    __shared__ float4 s_box[BOXES][2 * GRP_STRIDE];

    const int c   = blockIdx.y;
    const int tid = threadIdx.x;

    // ---- stage this class's 30 boxes, min/max-normalized, interleaved ----
    const float2* sb2 = reinterpret_cast<const float2*>(
        shape + (size_t)c * (BOXES * 2 * EMB));
    #pragma unroll
    for (int e = tid; e < BOXES * 32; e += 256) {
        const int box = e >> 5;
        const int j   = e & 31;
        const float2 a = sb2[box * 64 + j];        // corner 0, dims 2j,2j+1
        const float2 b = sb2[box * 64 + 32 + j];   // corner 1
        s_box[box][(j >> 4) * GRP_STRIDE + (j & 15)] =
            make_float4(fminf(a.x, b.x), fminf(a.y, b.y),
                        fmaxf(a.x, b.x), fmaxf(a.y, b.y));
    }

    // ---- data passthrough (class-slice 0 only): linear block copy ----
    if (blockIdx.y == 0) {
        // this block covers 128 points = 8192 floats = 2048 float4
        const float4* src = reinterpret_cast<const float4*>(
            data + (size_t)blockIdx.x * 128 * EMB);
        float4* dst = reinterpret_cast<float4*>(
            out + (size_t)blockIdx.x * 128 * EMB);
        #pragma unroll
        for (int k = 0; k < 8; k++)
            dst[tid + 256 * k] = src[tid + 256 * k];
    }
    __syncthreads();

    // ---- 2 threads per point: lane = g*16 + i ----
    const int lane = tid & 31;
    const int warp = tid >> 5;
    const int g    = lane >> 4;   // dim group: dims [g*32, g*32+32)
    const int i    = lane & 15;   // point within warp's 16
    const int n    = blockIdx.x * 128 + warp * 16 + i;

    // 32 dims = 16 packed f32x2
    u64 p[16];
    const ulonglong2* dp = reinterpret_cast<const ulonglong2*>(
        data + (size_t)n * EMB + g * 32);
    #pragma unroll
    for (int k = 0; k < 8; k++) {
        const ulonglong2 v = dp[k];
        p[2 * k]     = v.x;
        p[2 * k + 1] = v.y;
    }

    float* __restrict__ out_dists = out + OUT_DISTS
                                  + (size_t)c * BOXES * N_POINTS + n;

    bool town = false;
    #pragma unroll 1
    for (int h = 0; h < NUM_HOUSES; h++) {
        bool anyw = false, frame = false;
        #pragma unroll
        for (int w = 0; w < NUM_WIN; w++) {
            const int box = h * NUM_WIN + w;
            const float4* bx = &s_box[box][g * GRP_STRIDE];
            u64 a0, a1, a2, a3;
            PAIR_MUL(0, a0) PAIR_MUL(1, a1) PAIR_MUL(2, a2) PAIR_MUL(3, a3)
            #pragma unroll
            for (int j = 4; j < 16; j += 4) {
                PAIR_FMA(j + 0, a0)
                PAIR_FMA(j + 1, a1)
                PAIR_FMA(j + 2, a2)
                PAIR_FMA(j + 3, a3)
            }
            const u64 s = f32x2_add(f32x2_add(a0, a1), f32x2_add(a2, a3));
            float sx, sy; unpack2(s, sx, sy);
            float sq = sx + sy;
            // combine the two 32-dim halves (lanes xor 16)
            sq += __shfl_xor_sync(0xffffffffu, sq, 16);

            // inside <=> clamped == p in every dim <=> sq == 0 (exact;
            // both partials >= 0, so total 0 iff both are 0)
            const bool ins = (sq == 0.0f);
            if (w < NUM_WIN - 1) anyw |= ins;
            else                 frame = ins;

            if (g == 0) {
                float dist;
                asm("sqrt.approx.f32 %0, %1;" : "=f"(dist) : "f"(sq));
                out_dists[(size_t)box * N_POINTS] = dist;
            }
        }
        town |= (frame && !anyw);
    }

    if (g == 0)
        out[OUT_CONTAINS + (size_t)c * N_POINTS + n] = town ? 1.0f : 0.0f;
}

extern "C" void kernel_launch(void* const* d_in, const int* in_sizes, int n_in,
                              void* d_out, int out_size) {
    const float* data  = (const float*)d_in[0];
    const float* shape = (const float*)d_in[1];
    float* out = (float*)d_out;

    dim3 grid(N_POINTS / 128, NUM_CLASSES);
    geom_kernel<<<grid, 256>>>(data, shape, out);
}